// round 1
// baseline (speedup 1.0000x reference)
#include <cuda_runtime.h>

#define NN 100000
#define NE 1600000
#define INC 128
#define HID 64
#define OUTC 40

// ---------------- scratch (static __device__, no allocs) ----------------
__device__ float g_h[NN * 64];          // GEMM output (pre-aggregate)
__device__ float g_agg[NN * 64];        // aggregated output
__device__ int2  g_edges[NE];           // CSR payload: {src, __float_as_int(edge_norm)}
__device__ int   g_rowptr[NN + 1];
__device__ int   g_cnt[NN];
__device__ int   g_cur[NN];
__device__ float g_dis[NN];
__device__ float g_selfnorm[NN];
__device__ float g_sum[64], g_sumsq[64];
__device__ float g_bnA[64], g_bnB[64];
__device__ int   g_bsum[128], g_boff[128];
__device__ int   g_is64;

// ---------------- small utility kernels ----------------
__global__ void k_detect(const void* ei) {
    // if edge_index stored as int64 (values < 2^31), every odd 32-bit word is 0
    const int* p = (const int*)ei;
    int allz = 1;
    for (int i = 0; i < 64; i++)
        if (p[2 * i + 1] != 0) allz = 0;
    g_is64 = allz;
}

__device__ __forceinline__ int edge_idx(const void* ei, int i, int is64) {
    return is64 ? (int)((const long long*)ei)[i] : ((const int*)ei)[i];
}

__global__ void k_zero_counts() {
    int i = blockIdx.x * blockDim.x + threadIdx.x;
    if (i < NN) { g_cnt[i] = 0; g_cur[i] = 0; }
}

__global__ void k_zero_stats() {
    int i = threadIdx.x;
    if (i < 64) { g_sum[i] = 0.f; g_sumsq[i] = 0.f; }
}

__global__ void k_hist(const void* ei) {
    int e = blockIdx.x * blockDim.x + threadIdx.x;
    if (e >= NE) return;
    int is64 = g_is64;
    int d = edge_idx(ei, NE + e, is64);
    atomicAdd(&g_cnt[d], 1);
}

__global__ void k_nodeinit() {
    int n = blockIdx.x * blockDim.x + threadIdx.x;
    if (n >= NN) return;
    float deg = (float)g_cnt[n] + 1.0f;
    g_dis[n] = rsqrtf(deg);
    g_selfnorm[n] = 1.0f / deg;
}

// ---------------- 3-phase exclusive scan over g_cnt -> g_rowptr ----------------
__global__ void k_scan1() {
    __shared__ int s[1024];
    int t = threadIdx.x;
    int gid = blockIdx.x * 1024 + t;
    int v = (gid < NN) ? g_cnt[gid] : 0;
    s[t] = v;
    __syncthreads();
#pragma unroll
    for (int off = 1; off < 1024; off <<= 1) {
        int x = (t >= off) ? s[t - off] : 0;
        __syncthreads();
        s[t] += x;
        __syncthreads();
    }
    if (gid < NN) g_rowptr[gid] = s[t] - v;   // exclusive
    if (t == 1023) g_bsum[blockIdx.x] = s[t];
}

__global__ void k_scan2(int nb) {
    __shared__ int s[128];
    int t = threadIdx.x;
    int v = (t < nb) ? g_bsum[t] : 0;
    s[t] = v;
    __syncthreads();
#pragma unroll
    for (int off = 1; off < 128; off <<= 1) {
        int x = (t >= off) ? s[t - off] : 0;
        __syncthreads();
        s[t] += x;
        __syncthreads();
    }
    if (t < nb) g_boff[t] = s[t] - v;
}

__global__ void k_scan3() {
    int gid = blockIdx.x * blockDim.x + threadIdx.x;
    if (gid < NN) g_rowptr[gid] += g_boff[gid >> 10];
    if (gid == 0) g_rowptr[NN] = NE;
}

__global__ void k_fill(const void* ei) {
    int e = blockIdx.x * blockDim.x + threadIdx.x;
    if (e >= NE) return;
    int is64 = g_is64;
    int s = edge_idx(ei, e, is64);
    int d = edge_idx(ei, NE + e, is64);
    int pos = g_rowptr[d] + atomicAdd(&g_cur[d], 1);
    float w = g_dis[s] * g_dis[d];
    g_edges[pos] = make_int2(s, __float_as_int(w));
}

// ---------------- GEMM: out[M,N] = act(A)[M,K] @ W[K,N] + bias ----------------
// act = identity (useBN=0) or BN+ReLU using g_bnA/g_bnB (useBN=1), applied on load.
// BM=128, BN(padded)=64, 256 threads, TM=8, TN=4.
template <int K>
__global__ __launch_bounds__(256) void k_gemm(const float* __restrict__ A,
                                              const float* __restrict__ W,
                                              const float* __restrict__ bias,
                                              float* __restrict__ out,
                                              int N, int useBN) {
    __shared__ float Ws[K * 64];
    __shared__ float As[16 * 132];
    __shared__ float sA[K], sB[K];

    int tid = threadIdx.x;
    for (int i = tid; i < K * 64; i += 256) {
        int k = i >> 6, n = i & 63;
        Ws[i] = (n < N) ? W[k * N + n] : 0.f;
    }
    if (useBN) {
        for (int i = tid; i < K; i += 256) { sA[i] = g_bnA[i]; sB[i] = g_bnB[i]; }
    }
    float acc[8][4];
#pragma unroll
    for (int i = 0; i < 8; i++)
#pragma unroll
        for (int j = 0; j < 4; j++) acc[i][j] = 0.f;

    int tr = tid >> 4, tc = tid & 15;
    int m0 = blockIdx.x * 128;
    __syncthreads();

    for (int k0 = 0; k0 < K; k0 += 16) {
#pragma unroll
        for (int i = 0; i < 2; i++) {
            int v = tid + i * 256;          // 0..511
            int row = v >> 2;               // 0..127
            int kq = (v & 3) << 2;          // 0,4,8,12
            int m = m0 + row;
            if (m > NN - 1) m = NN - 1;
            float4 av = *(const float4*)(A + (size_t)m * K + k0 + kq);
            if (useBN) {
                av.x = fmaxf(fmaf(av.x, sA[k0 + kq + 0], sB[k0 + kq + 0]), 0.f);
                av.y = fmaxf(fmaf(av.y, sA[k0 + kq + 1], sB[k0 + kq + 1]), 0.f);
                av.z = fmaxf(fmaf(av.z, sA[k0 + kq + 2], sB[k0 + kq + 2]), 0.f);
                av.w = fmaxf(fmaf(av.w, sA[k0 + kq + 3], sB[k0 + kq + 3]), 0.f);
            }
            As[(kq + 0) * 132 + row] = av.x;
            As[(kq + 1) * 132 + row] = av.y;
            As[(kq + 2) * 132 + row] = av.z;
            As[(kq + 3) * 132 + row] = av.w;
        }
        __syncthreads();
#pragma unroll
        for (int kk = 0; kk < 16; kk++) {
            float4 b = *(const float4*)&Ws[(k0 + kk) * 64 + tc * 4];
            float a[8];
            *(float4*)&a[0] = *(const float4*)&As[kk * 132 + tr * 8];
            *(float4*)&a[4] = *(const float4*)&As[kk * 132 + tr * 8 + 4];
#pragma unroll
            for (int i = 0; i < 8; i++) {
                acc[i][0] = fmaf(a[i], b.x, acc[i][0]);
                acc[i][1] = fmaf(a[i], b.y, acc[i][1]);
                acc[i][2] = fmaf(a[i], b.z, acc[i][2]);
                acc[i][3] = fmaf(a[i], b.w, acc[i][3]);
            }
        }
        __syncthreads();
    }

    int col = tc * 4;
    if (col < N) {   // N is a multiple of 4, so col<N => col+3<N
        float4 bv = *(const float4*)(bias + col);
#pragma unroll
        for (int i = 0; i < 8; i++) {
            int m = m0 + tr * 8 + i;
            if (m < NN) {
                float4 o;
                o.x = acc[i][0] + bv.x;
                o.y = acc[i][1] + bv.y;
                o.z = acc[i][2] + bv.z;
                o.w = acc[i][3] + bv.w;
                *(float4*)(out + (size_t)m * N + col) = o;
            }
        }
    }
}

// ---------------- aggregate: out[n] = sum_e norm_e * h[src_e] + selfnorm[n]*h[n] ----------------
// warp per node, lane c = lane (+32)
template <int C>
__global__ __launch_bounds__(256) void k_aggregate(const float* __restrict__ h,
                                                   float* __restrict__ out) {
    int warp = (blockIdx.x * blockDim.x + threadIdx.x) >> 5;
    int lane = threadIdx.x & 31;
    if (warp >= NN) return;
    int beg = g_rowptr[warp];
    int end = g_rowptr[warp + 1];
    float acc0 = 0.f, acc1 = 0.f;
    const int c1 = lane + 32;
    for (int e = beg; e < end; e++) {
        int2 ed = g_edges[e];
        float w = __int_as_float(ed.y);
        const float* hr = h + (size_t)ed.x * C;
        acc0 = fmaf(w, hr[lane], acc0);
        if (C > 32 && c1 < C) acc1 = fmaf(w, hr[c1], acc1);
    }
    float sn = g_selfnorm[warp];
    const float* hs = h + (size_t)warp * C;
    acc0 = fmaf(sn, hs[lane], acc0);
    out[(size_t)warp * C + lane] = acc0;
    if (C > 32 && c1 < C) {
        acc1 = fmaf(sn, hs[c1], acc1);
        out[(size_t)warp * C + c1] = acc1;
    }
}

// ---------------- BN stats over g_agg (C=64 only) ----------------
__global__ __launch_bounds__(256) void k_stats(const float* __restrict__ a) {
    __shared__ float ssum[256], ssq[256];
    int c = threadIdx.x & 63;
    int ro = threadIdx.x >> 6;   // 0..3
    float s = 0.f, q = 0.f;
    for (int n = blockIdx.x * 4 + ro; n < NN; n += gridDim.x * 4) {
        float v = a[(size_t)n * 64 + c];
        s += v;
        q = fmaf(v, v, q);
    }
    ssum[threadIdx.x] = s;
    ssq[threadIdx.x] = q;
    __syncthreads();
    if (threadIdx.x < 64) {
        s = ssum[threadIdx.x] + ssum[threadIdx.x + 64] + ssum[threadIdx.x + 128] + ssum[threadIdx.x + 192];
        q = ssq[threadIdx.x] + ssq[threadIdx.x + 64] + ssq[threadIdx.x + 128] + ssq[threadIdx.x + 192];
        atomicAdd(&g_sum[c], s);
        atomicAdd(&g_sumsq[c], q);
    }
}

__global__ void k_bnfin(const float* __restrict__ g, const float* __restrict__ be) {
    int c = threadIdx.x;
    if (c < 64) {
        float mu = g_sum[c] * (1.0f / NN);
        float var = g_sumsq[c] * (1.0f / NN) - mu * mu;
        float a = g[c] * rsqrtf(var + 1e-5f);
        g_bnA[c] = a;
        g_bnB[c] = be[c] - mu * a;
    }
}

// ---------------- launch ----------------
extern "C" void kernel_launch(void* const* d_in, const int* in_sizes, int n_in,
                              void* d_out, int out_size) {
    const float* x  = (const float*)d_in[0];
    const void*  ei = d_in[1];
    const float* W1 = (const float*)d_in[2];
    const float* b1 = (const float*)d_in[3];
    const float* g1 = (const float*)d_in[4];
    const float* be1 = (const float*)d_in[5];
    const float* W2 = (const float*)d_in[6];
    const float* b2 = (const float*)d_in[7];
    const float* g2 = (const float*)d_in[8];
    const float* be2 = (const float*)d_in[9];
    const float* W3 = (const float*)d_in[10];
    const float* b3 = (const float*)d_in[11];
    float* out = (float*)d_out;

    float* h   = nullptr;
    float* agg = nullptr;
    cudaGetSymbolAddress((void**)&h, g_h);
    cudaGetSymbolAddress((void**)&agg, g_agg);

    const int EB = (NE + 255) / 256;
    const int NB = (NN + 255) / 256;
    const int SB = (NN + 1023) / 1024;        // 98
    const int GB = (NN + 127) / 128;          // 782
    const int AB = (NN * 32 + 255) / 256;     // 12500

    // ---- CSR build ----
    k_detect<<<1, 1>>>(ei);
    k_zero_counts<<<NB, 256>>>();
    k_hist<<<EB, 256>>>(ei);
    k_nodeinit<<<NB, 256>>>();
    k_scan1<<<SB, 1024>>>();
    k_scan2<<<1, 128>>>(SB);
    k_scan3<<<NB, 256>>>();
    k_fill<<<EB, 256>>>(ei);

    // ---- layer 1 ----
    k_gemm<128><<<GB, 256>>>(x, W1, b1, h, 64, 0);
    k_aggregate<64><<<AB, 256>>>(h, agg);
    k_zero_stats<<<1, 128>>>();
    k_stats<<<296, 256>>>(agg);
    k_bnfin<<<1, 64>>>(g1, be1);

    // ---- layer 2 ----
    k_gemm<64><<<GB, 256>>>(agg, W2, b2, h, 64, 1);
    k_aggregate<64><<<AB, 256>>>(h, agg);
    k_zero_stats<<<1, 128>>>();
    k_stats<<<296, 256>>>(agg);
    k_bnfin<<<1, 64>>>(g2, be2);

    // ---- layer 3 ----
    k_gemm<64><<<GB, 256>>>(agg, W3, b3, h, 40, 1);
    k_aggregate<40><<<AB, 256>>>(h, out);
}

// round 2
// speedup vs baseline: 1.1162x; 1.1162x over previous
#include <cuda_runtime.h>

#define NN 100000
#define NE 1600000

// ---------------- scratch (static __device__, no allocs) ----------------
__device__ float g_h[NN * 64];          // GEMM output (pre-aggregate)
__device__ float g_agg[NN * 64];        // aggregated output
__device__ int2  g_edges[NE];           // CSR payload: {src, __float_as_int(edge_norm)}
__device__ int   g_rowptr[NN + 1];
__device__ int   g_cnt[NN];
__device__ int   g_cur[NN];
__device__ float g_dis[NN];
__device__ float g_selfnorm[NN];
__device__ float g_stats[128];          // [0:64) sum, [64:128) sumsq
__device__ float g_bnA[64], g_bnB[64];
__device__ int   g_bsum[128], g_boff[128];
__device__ int   g_is64;

// ---------------- helpers ----------------
__device__ __forceinline__ unsigned f2tf32(float x) {
    unsigned r;
    asm("cvt.rna.tf32.f32 %0, %1;" : "=r"(r) : "f"(x));
    return r;
}

__device__ __forceinline__ void mma_tf32(float* d, const unsigned* a, const unsigned* b) {
    asm volatile(
        "mma.sync.aligned.m16n8k8.row.col.f32.tf32.tf32.f32 "
        "{%0,%1,%2,%3}, {%4,%5,%6,%7}, {%8,%9}, {%0,%1,%2,%3};"
        : "+f"(d[0]), "+f"(d[1]), "+f"(d[2]), "+f"(d[3])
        : "r"(a[0]), "r"(a[1]), "r"(a[2]), "r"(a[3]), "r"(b[0]), "r"(b[1]));
}

// ---------------- small utility kernels ----------------
__global__ void k_detect(const void* ei) {
    // int64 edge_index with values < 2^31 => every odd 32-bit word is 0
    const int* p = (const int*)ei;
    int nz = p[2 * threadIdx.x + 1] != 0;
    unsigned m = __ballot_sync(0xffffffffu, nz);
    if (threadIdx.x == 0) g_is64 = (m == 0);
}

__device__ __forceinline__ int edge_idx(const void* ei, int i, int is64) {
    return is64 ? (int)((const long long*)ei)[i] : ((const int*)ei)[i];
}

__global__ void k_hist(const void* ei) {
    int e = blockIdx.x * blockDim.x + threadIdx.x;
    if (e >= NE) return;
    int is64 = g_is64;
    int d = edge_idx(ei, NE + e, is64);
    atomicAdd(&g_cnt[d], 1);
}

// ---------------- 3-phase exclusive scan over g_cnt -> g_rowptr ----------------
__global__ void k_scan1() {
    __shared__ int s[1024];
    int t = threadIdx.x;
    int gid = blockIdx.x * 1024 + t;
    int v = (gid < NN) ? g_cnt[gid] : 0;
    s[t] = v;
    __syncthreads();
#pragma unroll
    for (int off = 1; off < 1024; off <<= 1) {
        int x = (t >= off) ? s[t - off] : 0;
        __syncthreads();
        s[t] += x;
        __syncthreads();
    }
    if (gid < NN) g_rowptr[gid] = s[t] - v;   // exclusive
    if (t == 1023) g_bsum[blockIdx.x] = s[t];
}

__global__ void k_scan2(int nb) {
    __shared__ int s[128];
    int t = threadIdx.x;
    int v = (t < nb) ? g_bsum[t] : 0;
    s[t] = v;
    __syncthreads();
#pragma unroll
    for (int off = 1; off < 128; off <<= 1) {
        int x = (t >= off) ? s[t - off] : 0;
        __syncthreads();
        s[t] += x;
        __syncthreads();
    }
    if (t < nb) g_boff[t] = s[t] - v;
}

// scan finalize + node init (deg-derived terms) fused
__global__ void k_scan3() {
    int gid = blockIdx.x * blockDim.x + threadIdx.x;
    if (gid < NN) {
        g_rowptr[gid] += g_boff[gid >> 10];
        float deg = (float)g_cnt[gid] + 1.0f;
        g_dis[gid] = rsqrtf(deg);
        g_selfnorm[gid] = 1.0f / deg;
    }
    if (gid == 0) g_rowptr[NN] = NE;
}

__global__ void k_fill(const void* ei) {
    int e = blockIdx.x * blockDim.x + threadIdx.x;
    if (e >= NE) return;
    int is64 = g_is64;
    int s = edge_idx(ei, e, is64);
    int d = edge_idx(ei, NE + e, is64);
    int pos = g_rowptr[d] + atomicAdd(&g_cur[d], 1);
    float w = g_dis[s] * g_dis[d];
    g_edges[pos] = make_int2(s, __float_as_int(w));
}

// ---------------- tf32 MMA GEMM: out[M,N] = act(A)[M,K] @ W[K,N] + bias ----------------
// N = NT*8. Block: 128 rows x N cols, 256 threads (8 warps), warp w owns rows w*16..w*16+15.
// act = identity (useBN=0) or BN+ReLU from g_bnA/g_bnB applied on A load.
template <int K, int NT>
__global__ __launch_bounds__(256) void k_gemm(const float* __restrict__ A,
                                              const float* __restrict__ W,
                                              const float* __restrict__ bias,
                                              float* __restrict__ out,
                                              int useBN) {
    constexpr int N = NT * 8;
    constexpr int KS = K / 8;
    __shared__ unsigned Bp[KS * NT * 64];   // [kstep][ntile][lane][2] fragment layout
    __shared__ unsigned As[16 * 132];       // [k mod 16][row] tf32 bits
    __shared__ float sA[K], sB[K];

    int tid = threadIdx.x;
    int lane = tid & 31;
    int warp = tid >> 5;

    // permute + convert W into exact B-fragment layout (one-time per block)
    for (int i = tid; i < KS * NT * 32; i += 256) {
        int l = i & 31;
        int t = (i >> 5) % NT;
        int ks = i / (32 * NT);
        int kk = ks * 8 + (l & 3);
        int n = t * 8 + (l >> 2);
        Bp[i * 2 + 0] = f2tf32(W[kk * N + n]);
        Bp[i * 2 + 1] = f2tf32(W[(kk + 4) * N + n]);
    }
    if (useBN) {
        for (int i = tid; i < K; i += 256) { sA[i] = g_bnA[i]; sB[i] = g_bnB[i]; }
    }

    float acc[NT][4];
#pragma unroll
    for (int t = 0; t < NT; t++)
#pragma unroll
        for (int j = 0; j < 4; j++) acc[t][j] = 0.f;

    int m0 = blockIdx.x * 128;
    __syncthreads();

    for (int k0 = 0; k0 < K; k0 += 16) {
        // stage A chunk: 128 rows x 16 k, applying BN+ReLU then tf32 rounding
#pragma unroll
        for (int i = 0; i < 2; i++) {
            int v = tid + i * 256;          // 0..511
            int row = v >> 2;               // 0..127
            int kq = (v & 3) << 2;          // 0,4,8,12
            int m = m0 + row;
            if (m > NN - 1) m = NN - 1;
            float4 av = *(const float4*)(A + (size_t)m * K + k0 + kq);
            if (useBN) {
                av.x = fmaxf(fmaf(av.x, sA[k0 + kq + 0], sB[k0 + kq + 0]), 0.f);
                av.y = fmaxf(fmaf(av.y, sA[k0 + kq + 1], sB[k0 + kq + 1]), 0.f);
                av.z = fmaxf(fmaf(av.z, sA[k0 + kq + 2], sB[k0 + kq + 2]), 0.f);
                av.w = fmaxf(fmaf(av.w, sA[k0 + kq + 3], sB[k0 + kq + 3]), 0.f);
            }
            As[(kq + 0) * 132 + row] = f2tf32(av.x);
            As[(kq + 1) * 132 + row] = f2tf32(av.y);
            As[(kq + 2) * 132 + row] = f2tf32(av.z);
            As[(kq + 3) * 132 + row] = f2tf32(av.w);
        }
        __syncthreads();
#pragma unroll
        for (int s = 0; s < 2; s++) {       // two k8 substeps per 16-chunk
            int kb = s * 8;
            int r = warp * 16 + (lane >> 2);
            int c = kb + (lane & 3);
            unsigned a[4];
            a[0] = As[c * 132 + r];
            a[1] = As[c * 132 + r + 8];
            a[2] = As[(c + 4) * 132 + r];
            a[3] = As[(c + 4) * 132 + r + 8];
            const unsigned* bp = &Bp[(k0 / 8 + s) * NT * 64 + lane * 2];
#pragma unroll
            for (int t = 0; t < NT; t++) {
                unsigned b[2] = { bp[t * 64], bp[t * 64 + 1] };
                mma_tf32(acc[t], a, b);
            }
        }
        __syncthreads();
    }

    // epilogue: c0,c1 at (r, col..col+1); c2,c3 at (r+8, col..col+1)
    int r0 = m0 + warp * 16 + (lane >> 2);
    int c0 = (lane & 3) * 2;
#pragma unroll
    for (int t = 0; t < NT; t++) {
        int col = t * 8 + c0;
        float2 bv = *(const float2*)(bias + col);
        if (r0 < NN) {
            float2 o = { acc[t][0] + bv.x, acc[t][1] + bv.y };
            *(float2*)(out + (size_t)r0 * N + col) = o;
        }
        if (r0 + 8 < NN) {
            float2 o = { acc[t][2] + bv.x, acc[t][3] + bv.y };
            *(float2*)(out + (size_t)(r0 + 8) * N + col) = o;
        }
    }
}

// ---------------- aggregate: out[n] = sum_e norm_e * h[src_e] + selfnorm[n]*h[n] ----------------
template <int C>
__global__ __launch_bounds__(256) void k_aggregate(const float* __restrict__ h,
                                                   float* __restrict__ out) {
    int warp = (blockIdx.x * blockDim.x + threadIdx.x) >> 5;
    int lane = threadIdx.x & 31;
    if (warp >= NN) return;
    int beg = g_rowptr[warp];
    int end = g_rowptr[warp + 1];
    float acc0 = 0.f, acc1 = 0.f;
    const int c1 = lane + 32;
    int e = beg;
    for (; e + 1 < end; e += 2) {       // 2-edge unroll for MLP
        int2 e0 = g_edges[e];
        int2 e1 = g_edges[e + 1];
        float w0 = __int_as_float(e0.y);
        float w1 = __int_as_float(e1.y);
        const float* h0 = h + (size_t)e0.x * C;
        const float* h1 = h + (size_t)e1.x * C;
        float v00 = h0[lane], v10 = h1[lane];
        float v01 = 0.f, v11 = 0.f;
        if (C > 32 && c1 < C) { v01 = h0[c1]; v11 = h1[c1]; }
        acc0 = fmaf(w0, v00, acc0);
        acc0 = fmaf(w1, v10, acc0);
        acc1 = fmaf(w0, v01, acc1);
        acc1 = fmaf(w1, v11, acc1);
    }
    if (e < end) {
        int2 ed = g_edges[e];
        float w = __int_as_float(ed.y);
        const float* hr = h + (size_t)ed.x * C;
        acc0 = fmaf(w, hr[lane], acc0);
        if (C > 32 && c1 < C) acc1 = fmaf(w, hr[c1], acc1);
    }
    float sn = g_selfnorm[warp];
    const float* hs = h + (size_t)warp * C;
    acc0 = fmaf(sn, hs[lane], acc0);
    out[(size_t)warp * C + lane] = acc0;
    if (C > 32 && c1 < C) {
        acc1 = fmaf(sn, hs[c1], acc1);
        out[(size_t)warp * C + c1] = acc1;
    }
}

// ---------------- BN stats over agg (C=64) ----------------
__global__ __launch_bounds__(256) void k_stats(const float* __restrict__ a) {
    __shared__ float ssum[256], ssq[256];
    int c = threadIdx.x & 63;
    int ro = threadIdx.x >> 6;   // 0..3
    float s = 0.f, q = 0.f;
    for (int n = blockIdx.x * 4 + ro; n < NN; n += gridDim.x * 4) {
        float v = a[(size_t)n * 64 + c];
        s += v;
        q = fmaf(v, v, q);
    }
    ssum[threadIdx.x] = s;
    ssq[threadIdx.x] = q;
    __syncthreads();
    if (threadIdx.x < 64) {
        s = ssum[threadIdx.x] + ssum[threadIdx.x + 64] + ssum[threadIdx.x + 128] + ssum[threadIdx.x + 192];
        q = ssq[threadIdx.x] + ssq[threadIdx.x + 64] + ssq[threadIdx.x + 128] + ssq[threadIdx.x + 192];
        atomicAdd(&g_stats[c], s);
        atomicAdd(&g_stats[64 + c], q);
    }
}

__global__ void k_bnfin(const float* __restrict__ g, const float* __restrict__ be) {
    int c = threadIdx.x;
    if (c < 64) {
        float mu = g_stats[c] * (1.0f / NN);
        float var = g_stats[64 + c] * (1.0f / NN) - mu * mu;
        float a = g[c] * rsqrtf(var + 1e-5f);
        g_bnA[c] = a;
        g_bnB[c] = be[c] - mu * a;
    }
}

// ---------------- launch ----------------
extern "C" void kernel_launch(void* const* d_in, const int* in_sizes, int n_in,
                              void* d_out, int out_size) {
    const float* x  = (const float*)d_in[0];
    const void*  ei = d_in[1];
    const float* W1 = (const float*)d_in[2];
    const float* b1 = (const float*)d_in[3];
    const float* g1 = (const float*)d_in[4];
    const float* be1 = (const float*)d_in[5];
    const float* W2 = (const float*)d_in[6];
    const float* b2 = (const float*)d_in[7];
    const float* g2 = (const float*)d_in[8];
    const float* be2 = (const float*)d_in[9];
    const float* W3 = (const float*)d_in[10];
    const float* b3 = (const float*)d_in[11];
    float* out = (float*)d_out;

    float* h = nullptr;
    float* agg = nullptr;
    void* p_cnt = nullptr;
    void* p_cur = nullptr;
    void* p_stats = nullptr;
    cudaGetSymbolAddress((void**)&h, g_h);
    cudaGetSymbolAddress((void**)&agg, g_agg);
    cudaGetSymbolAddress(&p_cnt, g_cnt);
    cudaGetSymbolAddress(&p_cur, g_cur);
    cudaGetSymbolAddress(&p_stats, g_stats);

    const int EB = (NE + 255) / 256;
    const int NB = (NN + 255) / 256;
    const int SB = (NN + 1023) / 1024;        // 98
    const int GB = (NN + 127) / 128;          // 782
    const int AB = (NN * 32 + 255) / 256;     // 12500

    // ---- CSR build ----
    k_detect<<<1, 32>>>(ei);
    cudaMemsetAsync(p_cnt, 0, NN * sizeof(int));
    cudaMemsetAsync(p_cur, 0, NN * sizeof(int));
    k_hist<<<EB, 256>>>(ei);
    k_scan1<<<SB, 1024>>>();
    k_scan2<<<1, 128>>>(SB);
    k_scan3<<<NB, 256>>>();
    k_fill<<<EB, 256>>>(ei);

    // ---- layer 1 ----
    k_gemm<128, 8><<<GB, 256>>>(x, W1, b1, h, 0);
    k_aggregate<64><<<AB, 256>>>(h, agg);
    cudaMemsetAsync(p_stats, 0, 128 * sizeof(float));
    k_stats<<<296, 256>>>(agg);
    k_bnfin<<<1, 64>>>(g1, be1);

    // ---- layer 2 ----
    k_gemm<64, 8><<<GB, 256>>>(agg, W2, b2, h, 1);
    k_aggregate<64><<<AB, 256>>>(h, agg);
    cudaMemsetAsync(p_stats, 0, 128 * sizeof(float));
    k_stats<<<296, 256>>>(agg);
    k_bnfin<<<1, 64>>>(g2, be2);

    // ---- layer 3 ----
    k_gemm<64, 5><<<GB, 256>>>(agg, W3, b3, h, 1);
    k_aggregate<40><<<AB, 256>>>(h, out);
}